// round 1
// baseline (speedup 1.0000x reference)
#include <cuda_runtime.h>

// MLP_Interpolate: 4x nearest upsample + 2-layer MLP, fully fused.
// Key identity: for out pixel o, iy = o>>2 and rel = (2*(o&3)-3)/4, a global
// constant. So each input pixel's first-layer product base = f @ W1[0:64] is
// shared by its 4x4 output block; the rel terms are 16 fixed vectors.
//
// Layout: one thread per input pixel. CTA = 64 threads = half an input row.
// Grid = B*H*2 = 1024 CTAs.

namespace {

constexpr int Hh  = 128;
constexpr int Wd  = 128;
constexpr int Cc  = 64;
constexpr int OUT = 512;

__global__ __launch_bounds__(64, 4) void mlp_interp_kernel(
    const float* __restrict__ x,   // [B,64,128,128]
    const float* __restrict__ W1,  // [66,64]
    const float* __restrict__ b1,  // [64]
    const float* __restrict__ W2,  // [64,3]
    const float* __restrict__ b2,  // [3]
    float* __restrict__ out)       // [B,3,512,512]
{
    // ---- shared weights / precomputed rel vectors ----
    __shared__ float  w1s[64 * 64];    // W1[0:64][:], row-major (c, j)
    __shared__ float4 A4[4][16];       // A4[j][i] = rel_j*W1[64][4i..4i+3] + b1
    __shared__ float4 Bx4[4][16];      // Bx4[k][i] = rel_k*W1[65][4i..4i+3]
    __shared__ float4 W2T[3][16];      // W2T[ch][i] = W2[4i..4i+3][ch]
    __shared__ float  b2s[4];

    const int tid = threadIdx.x;
    const int cta = blockIdx.x;
    const int w   = ((cta & 1) << 6) + tid;   // input col 0..127
    const int bh  = cta >> 1;
    const int h   = bh & (Hh - 1);
    const int b   = bh >> 7;

    // fill w1s (4096 floats, 64 floats per thread, coalesced)
    #pragma unroll
    for (int i = 0; i < 64; i++) w1s[i * 64 + tid] = W1[i * 64 + tid];

    {
        const int c   = tid;                  // 64 threads, one c each
        const float w64 = W1[64 * 64 + c];
        const float w65 = W1[65 * 64 + c];
        const float bb  = b1[c];
        float* Af = (float*)A4;
        float* Bf = (float*)Bx4;
        float* Wf = (float*)W2T;
        #pragma unroll
        for (int j = 0; j < 4; j++) {
            const float rel = -0.75f + 0.5f * (float)j;
            Af[j * 64 + c] = fmaf(rel, w64, bb);
            Bf[j * 64 + c] = rel * w65;
        }
        #pragma unroll
        for (int ch = 0; ch < 3; ch++) Wf[ch * 64 + c] = W2[c * 3 + ch];
        if (c < 3) b2s[c] = b2[c];
    }
    __syncthreads();

    // ---- base = f @ W1[0:64]  (64 -> 64) ----
    const float* xp = x + (((size_t)b * Cc) * Hh + h) * Wd + w;

    float4 base[16];
    #pragma unroll
    for (int i = 0; i < 16; i++) base[i] = make_float4(0.f, 0.f, 0.f, 0.f);

    #pragma unroll 8
    for (int c = 0; c < 64; c++) {
        const float fc = __ldg(xp + (size_t)c * (Hh * Wd));
        const float4* wr = (const float4*)(w1s + c * 64);
        #pragma unroll
        for (int i = 0; i < 16; i++) {
            float4 wv = wr[i];
            base[i].x = fmaf(fc, wv.x, base[i].x);
            base[i].y = fmaf(fc, wv.y, base[i].y);
            base[i].z = fmaf(fc, wv.z, base[i].z);
            base[i].w = fmaf(fc, wv.w, base[i].w);
        }
    }

    // ---- epilogue: 16 output pixels (4 rows j, 4 cols k) ----
    float4* op = (float4*)out;
    const float bz0 = b2s[0], bz1 = b2s[1], bz2 = b2s[2];

    #pragma unroll 1
    for (int j = 0; j < 4; j++) {
        float acc0[4], acc1[4], acc2[4];
        #pragma unroll
        for (int k = 0; k < 4; k++) { acc0[k] = bz0; acc1[k] = bz1; acc2[k] = bz2; }

        #pragma unroll
        for (int i = 0; i < 16; i++) {
            const float4 bs  = base[i];
            const float4 aj  = A4[j][i];
            const float bx = bs.x + aj.x;
            const float by = bs.y + aj.y;
            const float bzv = bs.z + aj.z;
            const float bw = bs.w + aj.w;
            const float4 w20 = W2T[0][i];
            const float4 w21 = W2T[1][i];
            const float4 w22 = W2T[2][i];
            #pragma unroll
            for (int k = 0; k < 4; k++) {
                const float4 bk = Bx4[k][i];
                const float h0 = fmaxf(bx  + bk.x, 0.f);
                const float h1 = fmaxf(by  + bk.y, 0.f);
                const float h2 = fmaxf(bzv + bk.z, 0.f);
                const float h3 = fmaxf(bw  + bk.w, 0.f);
                acc0[k] = fmaf(h0, w20.x, fmaf(h1, w20.y, fmaf(h2, w20.z, fmaf(h3, w20.w, acc0[k]))));
                acc1[k] = fmaf(h0, w21.x, fmaf(h1, w21.y, fmaf(h2, w21.z, fmaf(h3, w21.w, acc1[k]))));
                acc2[k] = fmaf(h0, w22.x, fmaf(h1, w22.y, fmaf(h2, w22.z, fmaf(h3, w22.w, acc2[k]))));
            }
        }

        // store float4 per channel: out[b, ch, 4h+j, 4w..4w+3]
        const int row = 4 * h + j;
        const size_t rb = ((size_t)(b * 3) * OUT + row) * (OUT / 4) + w;
        op[rb]                                 = make_float4(acc0[0], acc0[1], acc0[2], acc0[3]);
        op[rb + (size_t)OUT * (OUT / 4)]       = make_float4(acc1[0], acc1[1], acc1[2], acc1[3]);
        op[rb + (size_t)2 * OUT * (OUT / 4)]   = make_float4(acc2[0], acc2[1], acc2[2], acc2[3]);
    }
}

}  // namespace

extern "C" void kernel_launch(void* const* d_in, const int* in_sizes, int n_in,
                              void* d_out, int out_size) {
    const float* x  = (const float*)d_in[0];
    const float* W1 = (const float*)d_in[1];
    const float* b1 = (const float*)d_in[2];
    const float* W2 = (const float*)d_in[3];
    const float* b2 = (const float*)d_in[4];
    float* out = (float*)d_out;

    // grid: B*H*2 = 4*128*2 = 1024 CTAs, 64 threads (one input pixel each)
    mlp_interp_kernel<<<1024, 64>>>(x, W1, b1, W2, b2, out);
}

// round 2
// speedup vs baseline: 3.6128x; 3.6128x over previous
#include <cuda_runtime.h>

// MLP_Interpolate: 4x nearest upsample + 2-layer MLP, fused, hidden-chunked.
//
// Identity: iy = o>>2, rel = (2*(o&3)-3)/4 (global constants). Per input pixel,
// first-layer output h[j,k][i] = base[i] + A_j[i] + B_k[i] with
// base = f @ W1[0:64], A_j = rel_j*W1[64] + b1, B_k = rel_k*W1[65].
// relu is elementwise in i, so the second layer accumulates over i in 4
// chunks of 16 -> only 16 regs of "base" live at a time; final accs = 48 regs.

namespace {

constexpr int Hh = 128;
constexpr int Wd = 128;
constexpr int HW = Hh * Wd;
constexpr int OUT = 512;

__global__ __launch_bounds__(128, 4) void mlp_interp_kernel(
    const float* __restrict__ x,   // [B,64,128,128]
    const float* __restrict__ W1,  // [66,64]
    const float* __restrict__ b1,  // [64]
    const float* __restrict__ W2,  // [64,3]
    const float* __restrict__ b2,  // [3]
    float* __restrict__ out)       // [B,3,512,512]
{
    __shared__ float  w1s[64 * 64];   // W1[0:64][:] row-major (c, i)
    __shared__ float4 A4[4][16];      // A4[j][g] = rel_j*W1[64][4g..] + b1
    __shared__ float4 Bx4[4][16];     // Bx4[k][g] = rel_k*W1[65][4g..]
    __shared__ float4 W2T[3][16];     // W2T[ch][g] = W2[4g..4g+3][ch]
    __shared__ float  b2s[4];

    const int tid = threadIdx.x;      // input col w = tid
    const int cta = blockIdx.x;       // 512 CTAs: b*128 + h
    const int h   = cta & (Hh - 1);
    const int b   = cta >> 7;

    // stage W1[0:64] (4096 floats, 32 per thread, coalesced)
    #pragma unroll
    for (int r = 0; r < 32; r++) w1s[r * 128 + tid] = W1[r * 128 + tid];

    if (tid < 64) {
        const int c = tid;
        const float w64 = W1[64 * 64 + c];
        const float w65 = W1[64 * 64 + 64 + c];
        const float bb  = b1[c];
        float* Af = (float*)A4;
        float* Bf = (float*)Bx4;
        float* Wf = (float*)W2T;
        #pragma unroll
        for (int j = 0; j < 4; j++) {
            const float rel = -0.75f + 0.5f * (float)j;
            Af[j * 64 + c] = fmaf(rel, w64, bb);
            Bf[j * 64 + c] = rel * w65;
        }
        #pragma unroll
        for (int ch = 0; ch < 3; ch++) Wf[ch * 64 + c] = W2[c * 3 + ch];
        if (c < 3) b2s[c] = b2[c];
    }
    __syncthreads();

    const float* xp = x + (size_t)b * 64 * HW + h * Wd + tid;

    // final accumulators: acc[ch][j].{x,y,z,w} = output (ch, row j, col k)
    float4 acc[3][4];
    #pragma unroll
    for (int ch = 0; ch < 3; ch++) {
        const float bv = b2s[ch];
        #pragma unroll
        for (int j = 0; j < 4; j++) acc[ch][j] = make_float4(bv, bv, bv, bv);
    }

    #pragma unroll 1
    for (int chunk = 0; chunk < 4; chunk++) {
        // ---- bc[i] = partial base for hidden dims [chunk*16, chunk*16+16) ----
        float4 bc[4];
        #pragma unroll
        for (int i = 0; i < 4; i++) bc[i] = make_float4(0.f, 0.f, 0.f, 0.f);

        #pragma unroll 8
        for (int c = 0; c < 64; c++) {
            const float fc = xp[(size_t)c * HW];   // L1-hit after chunk 0
            const float4* wr = (const float4*)(w1s + c * 64 + chunk * 16);
            #pragma unroll
            for (int i = 0; i < 4; i++) {
                const float4 wv = wr[i];           // warp-uniform -> broadcast
                bc[i].x = fmaf(fc, wv.x, bc[i].x);
                bc[i].y = fmaf(fc, wv.y, bc[i].y);
                bc[i].z = fmaf(fc, wv.z, bc[i].z);
                bc[i].w = fmaf(fc, wv.w, bc[i].w);
            }
        }

        // ---- epilogue: fold this chunk into all 16 output pixels ----
        #pragma unroll
        for (int j = 0; j < 4; j++) {
            #pragma unroll
            for (int i = 0; i < 4; i++) {
                const int g = chunk * 4 + i;
                const float4 aj = A4[j][g];
                const float tx = bc[i].x + aj.x;
                const float ty = bc[i].y + aj.y;
                const float tz = bc[i].z + aj.z;
                const float tw = bc[i].w + aj.w;
                const float4 w0  = W2T[0][g];
                const float4 w1v = W2T[1][g];
                const float4 w2v = W2T[2][g];

#define EPI_K(KK, COMP)                                                          \
                do {                                                             \
                    const float4 bk = Bx4[KK][g];                                \
                    const float h0 = fmaxf(tx + bk.x, 0.f);                      \
                    const float h1 = fmaxf(ty + bk.y, 0.f);                      \
                    const float h2 = fmaxf(tz + bk.z, 0.f);                      \
                    const float h3 = fmaxf(tw + bk.w, 0.f);                      \
                    acc[0][j].COMP = fmaf(h0, w0.x,  fmaf(h1, w0.y,              \
                                     fmaf(h2, w0.z,  fmaf(h3, w0.w,  acc[0][j].COMP)))); \
                    acc[1][j].COMP = fmaf(h0, w1v.x, fmaf(h1, w1v.y,             \
                                     fmaf(h2, w1v.z, fmaf(h3, w1v.w, acc[1][j].COMP)))); \
                    acc[2][j].COMP = fmaf(h0, w2v.x, fmaf(h1, w2v.y,             \
                                     fmaf(h2, w2v.z, fmaf(h3, w2v.w, acc[2][j].COMP)))); \
                } while (0)

                EPI_K(0, x);
                EPI_K(1, y);
                EPI_K(2, z);
                EPI_K(3, w);
#undef EPI_K
            }
        }
    }

    // ---- stores: out[b, ch, 4h+j, 4*tid .. 4*tid+3] as float4, coalesced ----
    float4* op = (float4*)out;
    #pragma unroll
    for (int ch = 0; ch < 3; ch++) {
        #pragma unroll
        for (int j = 0; j < 4; j++) {
            const size_t idx = ((size_t)(b * 3 + ch) * OUT + (4 * h + j)) * (OUT / 4) + tid;
            op[idx] = acc[ch][j];
        }
    }
}

}  // namespace

extern "C" void kernel_launch(void* const* d_in, const int* in_sizes, int n_in,
                              void* d_out, int out_size) {
    const float* x  = (const float*)d_in[0];
    const float* W1 = (const float*)d_in[1];
    const float* b1 = (const float*)d_in[2];
    const float* W2 = (const float*)d_in[3];
    const float* b2 = (const float*)d_in[4];
    float* out = (float*)d_out;

    // 512 CTAs (one input row each), 128 threads (one input pixel each)
    mlp_interp_kernel<<<512, 128>>>(x, W1, b1, W2, b2, out);
}

// round 3
// speedup vs baseline: 4.0354x; 1.1170x over previous
#include <cuda_runtime.h>

// MLP_Interpolate: 4x nearest upsample + 2-layer MLP, fused, f32x2-packed.
//
// Identities: iy = o>>2; rel = (2*(o&3)-3)/4 are global constants. Per input
// pixel: h[j,k][i] = relu(base[i] + C[j][k][i]) with base = f @ W1[0:64] and
// C[j][k][i] = rel_j*W1[64][i] + rel_k*W1[65][i] + b1[i]  (precomputed, smem).
// out[ch][j][k] = b2[ch] + sum_i h[j,k][i] * W2[i][ch].
//
// All heavy math uses sm_103a packed f32x2 (2 lanes per fma-pipe instr):
//  - base GEMM: accumulators packed over hidden-dim pairs
//  - epilogue: packed over output-column pairs (k0,k1),(k2,k3)

namespace {

typedef unsigned long long ull;

__device__ __forceinline__ ull pk(float lo, float hi) {
    ull r; asm("mov.b64 %0, {%1, %2};" : "=l"(r) : "f"(lo), "f"(hi)); return r;
}
__device__ __forceinline__ float2 upk(ull a) {
    float2 r; asm("mov.b64 {%0, %1}, %2;" : "=f"(r.x), "=f"(r.y) : "l"(a)); return r;
}
__device__ __forceinline__ ull addx2(ull a, ull b) {
    ull d; asm("add.rn.f32x2 %0, %1, %2;" : "=l"(d) : "l"(a), "l"(b)); return d;
}
__device__ __forceinline__ ull fmax2(ull a, ull b, ull c) {
    ull d; asm("fma.rn.f32x2 %0, %1, %2, %3;" : "=l"(d) : "l"(a), "l"(b), "l"(c)); return d;
}
__device__ __forceinline__ ull relu2(ull s) {   // FMNMX on halves (alu pipe)
    float2 v = upk(s);
    return pk(fmaxf(v.x, 0.f), fmaxf(v.y, 0.f));
}

constexpr int Hh = 128;
constexpr int Wd = 128;
constexpr int HW = Hh * Wd;
constexpr int OUT = 512;

__global__ __launch_bounds__(128, 4) void mlp_interp_kernel(
    const float* __restrict__ x,   // [B,64,128,128]
    const float* __restrict__ W1,  // [66,64]
    const float* __restrict__ b1,  // [64]
    const float* __restrict__ W2,  // [64,3]
    const float* __restrict__ b2,  // [3]
    float* __restrict__ out)       // [B,3,512,512]
{
    __shared__ float      w1s[64 * 64];   // W1[0:64][:] row-major (c, i)
    __shared__ ulonglong2 Cp[4][64];      // Cp[j][i] = {(C[j][0][i],C[j][1][i]),(C[j][2][i],C[j][3][i])}
    __shared__ ull        W2d[64][3];     // W2d[i][ch] = (w, w) duplicated
    __shared__ float      b2s[4];

    const int tid = threadIdx.x;          // input col w = tid
    const int cta = blockIdx.x;           // 512 CTAs: b*128 + h
    const int h   = cta & (Hh - 1);
    const int b   = cta >> 7;

    // stage W1[0:64] (4096 floats, 32 per thread, coalesced)
    #pragma unroll
    for (int r = 0; r < 32; r++) w1s[r * 128 + tid] = W1[r * 128 + tid];

    if (tid < 64) {
        const int c = tid;
        const float w64 = W1[64 * 64 + c];
        const float w65 = W1[64 * 64 + 64 + c];
        const float bb  = b1[c];
        #pragma unroll
        for (int j = 0; j < 4; j++) {
            const float rj = -0.75f + 0.5f * (float)j;
            const float base = fmaf(rj, w64, bb);
            float cv[4];
            #pragma unroll
            for (int k = 0; k < 4; k++) {
                const float rk = -0.75f + 0.5f * (float)k;
                cv[k] = fmaf(rk, w65, base);
            }
            Cp[j][c].x = pk(cv[0], cv[1]);
            Cp[j][c].y = pk(cv[2], cv[3]);
        }
        #pragma unroll
        for (int ch = 0; ch < 3; ch++) {
            const float w = W2[c * 3 + ch];
            W2d[c][ch] = pk(w, w);
        }
        if (c < 3) b2s[c] = b2[c];
    }
    __syncthreads();

    const float* xp = x + (size_t)b * 64 * HW + h * Wd + tid;

    // final accumulators: acc[ch][j][kp] = packed (k=2kp, k=2kp+1)
    ull acc[3][4][2];
    #pragma unroll
    for (int ch = 0; ch < 3; ch++) {
        const ull bv = pk(b2s[ch], b2s[ch]);
        #pragma unroll
        for (int j = 0; j < 4; j++) { acc[ch][j][0] = bv; acc[ch][j][1] = bv; }
    }

    #pragma unroll 1
    for (int chunk = 0; chunk < 4; chunk++) {
        // ---- base (packed over hidden-dim pairs): dims [16*chunk, 16*chunk+16) ----
        ull bcp[8];
        #pragma unroll
        for (int p = 0; p < 8; p++) bcp[p] = 0ull;

        #pragma unroll 8
        for (int c = 0; c < 64; c++) {
            const float fc = xp[(size_t)c * HW];          // L1-hit after chunk 0
            const ull fcd = pk(fc, fc);
            const ulonglong2* wr =
                (const ulonglong2*)(w1s + c * 64 + chunk * 16);
            #pragma unroll
            for (int p = 0; p < 4; p++) {                 // 4x LDS.128, 8 packed fma
                const ulonglong2 wv = wr[p];
                bcp[2 * p]     = fmax2(fcd, wv.x, bcp[2 * p]);
                bcp[2 * p + 1] = fmax2(fcd, wv.y, bcp[2 * p + 1]);
            }
        }

        // ---- epilogue: fold 16 hidden dims into all 16 output pixels ----
        #pragma unroll
        for (int m = 0; m < 8; m++) {
            const float2 bcv = upk(bcp[m]);
            #pragma unroll
            for (int half = 0; half < 2; half++) {
                const int i = chunk * 16 + m * 2 + half;
                const float bs = half ? bcv.y : bcv.x;
                const ull bd = pk(bs, bs);
                const ull wd0 = W2d[i][0];
                const ull wd1 = W2d[i][1];
                const ull wd2 = W2d[i][2];
                #pragma unroll
                for (int j = 0; j < 4; j++) {
                    const ulonglong2 cc = Cp[j][i];       // 1x LDS.128
                    const ull h01 = relu2(addx2(bd, cc.x));
                    const ull h23 = relu2(addx2(bd, cc.y));
                    acc[0][j][0] = fmax2(h01, wd0, acc[0][j][0]);
                    acc[0][j][1] = fmax2(h23, wd0, acc[0][j][1]);
                    acc[1][j][0] = fmax2(h01, wd1, acc[1][j][0]);
                    acc[1][j][1] = fmax2(h23, wd1, acc[1][j][1]);
                    acc[2][j][0] = fmax2(h01, wd2, acc[2][j][0]);
                    acc[2][j][1] = fmax2(h23, wd2, acc[2][j][1]);
                }
            }
        }
    }

    // ---- stores: out[b, ch, 4h+j, 4*tid .. 4*tid+3] as float4, coalesced ----
    float4* op = (float4*)out;
    #pragma unroll
    for (int ch = 0; ch < 3; ch++) {
        #pragma unroll
        for (int j = 0; j < 4; j++) {
            const float2 a0 = upk(acc[ch][j][0]);
            const float2 a1 = upk(acc[ch][j][1]);
            const size_t idx =
                ((size_t)(b * 3 + ch) * OUT + (4 * h + j)) * (OUT / 4) + tid;
            op[idx] = make_float4(a0.x, a0.y, a1.x, a1.y);
        }
    }
}

}  // namespace

extern "C" void kernel_launch(void* const* d_in, const int* in_sizes, int n_in,
                              void* d_out, int out_size) {
    const float* x  = (const float*)d_in[0];
    const float* W1 = (const float*)d_in[1];
    const float* b1 = (const float*)d_in[2];
    const float* W2 = (const float*)d_in[3];
    const float* b2 = (const float*)d_in[4];
    float* out = (float*)d_out;

    mlp_interp_kernel<<<512, 128>>>(x, W1, b1, W2, b2, out);
}